// round 15
// baseline (speedup 1.0000x reference)
#include <cuda_runtime.h>
#include <cuda_fp16.h>
#include <cstdint>

#define THREADS 512
#define ROWS 96
#define SCALE 0.0048957583488887505f   // sqrt(pi/2)/256
#define TAU 2e-2f

// smem layout (bytes). fp16 row pitch 272B (conflict-free ldmatrix).
#define EST_OFF 0                      // float[96][8] = 3072
#define K_OFF   4096                   // 96 x 272 fp16
#define Q_OFF   (K_OFF + 26112)
#define F32_OFF (Q_OFF + 26112)        // fp32 staging: k 49152 + q 49152
#define F32Q    (F32_OFF + 49152)
#define S_OFF   (F32_OFF + 98304)      // S: 256 x 272 fp16
#define SMEM_TOTAL (S_OFF + 69632)     // 224256

__device__ __align__(16) unsigned char g_Sfp16[69632];

__device__ __forceinline__ uint32_t smem_u32(const void* p) {
    uint32_t a;
    asm("{ .reg .u64 t; cvta.to.shared.u64 t, %1; cvt.u32.u64 %0, t; }"
        : "=r"(a) : "l"(p));
    return a;
}
__device__ __forceinline__ uint32_t f16x2(float lo, float hi) {
    uint32_t r;
    asm("cvt.rn.f16x2.f32 %0, %1, %2;" : "=r"(r) : "f"(hi), "f"(lo));
    return r;
}
__device__ __forceinline__ void ldsm_x4(uint32_t* r, uint32_t a) {
    asm volatile("ldmatrix.sync.aligned.m8n8.x4.shared.b16 {%0,%1,%2,%3}, [%4];"
                 : "=r"(r[0]), "=r"(r[1]), "=r"(r[2]), "=r"(r[3]) : "r"(a));
}
__device__ __forceinline__ void mma16816(float* d, const uint32_t* a,
                                         uint32_t b0, uint32_t b1) {
    asm volatile(
        "mma.sync.aligned.m16n8k16.row.col.f32.f16.f16.f32 "
        "{%0,%1,%2,%3}, {%4,%5,%6,%7}, {%8,%9}, {%0,%1,%2,%3};"
        : "+f"(d[0]), "+f"(d[1]), "+f"(d[2]), "+f"(d[3])
        : "r"(a[0]), "r"(a[1]), "r"(a[2]), "r"(a[3]), "r"(b0), "r"(b1));
}
__device__ __forceinline__ void cp16(uint32_t saddr, const void* gaddr) {
    asm volatile("cp.async.cg.shared.global [%0], [%1], 16;"
                 :: "r"(saddr), "l"(gaddr) : "memory");
}

// ---------------------------------------------------------------------------
// Kernel 0: convert S (256x128 fp32) -> fp16 image with 272B row pitch.
// ---------------------------------------------------------------------------
__global__ void qjl_conv_S(const float* __restrict__ S) {
    int i = blockIdx.x * blockDim.x + threadIdx.x;  // 0..4095
    int row = i >> 4, g = i & 15;
    const float4* src = (const float4*)(S + (size_t)row * 128 + g * 8);
    float4 a = __ldg(src), b = __ldg(src + 1);
    uint4 o;
    o.x = f16x2(a.x, a.y); o.y = f16x2(a.z, a.w);
    o.z = f16x2(b.x, b.y); o.w = f16x2(b.z, b.w);
    *(uint4*)(g_Sfp16 + row * 272 + g * 16) = o;
}

// issue cp.async for one tile's fp32 k,q into staging (12 x 16B per thread)
__device__ __forceinline__ void issue_tile(uint32_t sb,
                                           const float* __restrict__ key,
                                           const float* __restrict__ qry,
                                           int tok_base, int ntok, int tid) {
    #pragma unroll
    for (int i = 0; i < 6; i++) {
        int u = tid + i * 512;                 // 16B group, u < 3072
        int row = u >> 5, c4 = u & 31;
        int tok = tok_base + row; if (tok >= ntok) tok = ntok - 1;
        cp16(sb + F32_OFF + u * 16, (const float4*)(key + (size_t)tok * 128) + c4);
        cp16(sb + F32Q    + u * 16, (const float4*)(qry + (size_t)tok * 128) + c4);
    }
    asm volatile("cp.async.commit_group;" ::: "memory");
}

// ---------------------------------------------------------------------------
// Main kernel: persistent, 1 CTA/SM, 512 threads, no specialization.
// cp.async fills fp32 staging for tile t+1 during compute of tile t.
// 16 warps in 2(M) x 8(N); warp tile 48 rows x 32 projections.
// ---------------------------------------------------------------------------
__global__ void __launch_bounds__(THREADS, 1)
qjl_fused(const float* __restrict__ qry, const float* __restrict__ key,
          const float* __restrict__ Sg, float* __restrict__ out,
          int ntok, int ntiles) {
    extern __shared__ char smem[];
    const uint32_t sb = smem_u32(smem);
    const int tid = threadIdx.x, wid = tid >> 5, l = tid & 31;
    const int wm = wid >> 3, wn = wid & 7;     // 2(M) x 8(N)

    // ---- prologue: S image + tile(0) fp32, both async ----
    for (int u = tid; u < 4352; u += THREADS)
        cp16(sb + S_OFF + u * 16, g_Sfp16 + u * 16);
    asm volatile("cp.async.commit_group;" ::: "memory");
    issue_tile(sb, key, qry, blockIdx.x * ROWS, ntok, tid);
    asm volatile("cp.async.wait_group 0;" ::: "memory");
    __syncthreads();

    const uint32_t a_base = sb + K_OFF + (uint32_t)wm * (48 * 272)
                          + (uint32_t)(l & 15) * 272 + (uint32_t)(l >> 4) * 16;
    const uint32_t b_base = sb + S_OFF + (uint32_t)wn * (32 * 272)
                          + (uint32_t)(l >> 4) * (8 * 272)
                          + (uint32_t)(l & 7) * 272 + (uint32_t)((l >> 3) & 1) * 16;

    for (int tile = blockIdx.x; tile < ntiles; tile += gridDim.x) {
        const int tok_base = tile * ROWS;

        // ---- convert staging fp32 -> fp16 K/Q images (all threads) ----
        #pragma unroll
        for (int i = 0; i < 6; i++) {
            int u = tid + i * 512;
            uint32_t doff = (uint32_t)(u >> 5) * 272 + (uint32_t)(u & 31) * 8;
            float4 v = *(const float4*)(smem + F32_OFF + u * 16);
            uint2 pk; pk.x = f16x2(v.x, v.y); pk.y = f16x2(v.z, v.w);
            *(uint2*)(smem + K_OFF + doff) = pk;
            float4 w = *(const float4*)(smem + F32Q + u * 16);
            uint2 pq; pq.x = f16x2(w.x, w.y); pq.y = f16x2(w.z, w.w);
            *(uint2*)(smem + Q_OFF + doff) = pq;
        }
        __syncthreads();   // converts done; staging free for refill

        // ---- issue next tile's fp32 loads (fills during compute) ----
        int nt_tile = tile + gridDim.x;
        if (nt_tile < ntiles)
            issue_tile(sb, key, qry, nt_tile * ROWS, ntok, tid);

        float acc[3][4][4];
        #pragma unroll
        for (int mt = 0; mt < 3; mt++)
            #pragma unroll
            for (int nt = 0; nt < 4; nt++)
                #pragma unroll
                for (int j = 0; j < 4; j++) acc[mt][nt][j] = 0.f;

        // ---- k-projection: 48x32 warp tile ----
        #pragma unroll
        for (int ks = 0; ks < 8; ks++) {
            uint32_t A[3][4];
            ldsm_x4(A[0], a_base + ks * 32);
            ldsm_x4(A[1], a_base + ks * 32 + 16 * 272);
            ldsm_x4(A[2], a_base + ks * 32 + 32 * 272);
            #pragma unroll
            for (int g = 0; g < 2; g++) {
                uint32_t B[4];
                ldsm_x4(B, b_base + g * (16 * 272) + ks * 32);
                #pragma unroll
                for (int mt = 0; mt < 3; mt++) {
                    mma16816(acc[mt][2 * g],     A[mt], B[0], B[1]);
                    mma16816(acc[mt][2 * g + 1], A[mt], B[2], B[3]);
                }
            }
        }

        // ---- signs + near-zero flags (48 slots) ----
        unsigned long long sign = 0ull, flag = 0ull;
        #pragma unroll
        for (int mt = 0; mt < 3; mt++)
            #pragma unroll
            for (int nt = 0; nt < 4; nt++)
                #pragma unroll
                for (int j = 0; j < 4; j++) {
                    int id = mt * 16 + nt * 4 + j;
                    float v = acc[mt][nt][j];
                    if (v > 0.f) sign |= 1ull << id;
                    if (fabsf(v) < TAU) flag |= 1ull << id;
                }

        // ---- warp-cooperative exact fp32 fixup ----
        for (;;) {
            uint32_t active = __ballot_sync(0xFFFFFFFFu, flag != 0ull);
            if (!active) break;
            int leader = __ffs(active) - 1;
            int tok = 0, proj = 0, id = 0;
            if (l == leader) {
                id = __ffsll(flag) - 1;
                int mt = id >> 4, j = id & 3;
                int nt = (id >> 2) & 3;
                int row = wm * 48 + mt * 16 + (l >> 2) + (j >> 1) * 8;
                tok = tok_base + row; if (tok >= ntok) tok = ntok - 1;
                proj = wn * 32 + nt * 8 + (l & 3) * 2 + (j & 1);
            }
            tok  = __shfl_sync(0xFFFFFFFFu, tok, leader);
            proj = __shfl_sync(0xFFFFFFFFu, proj, leader);
            const float* kr = key + (size_t)tok * 128 + l * 4;
            const float* sr = Sg + (size_t)proj * 128 + l * 4;
            float p = 0.f;
            #pragma unroll
            for (int d = 0; d < 4; d++) p = fmaf(__ldg(kr + d), __ldg(sr + d), p);
            #pragma unroll
            for (int off = 16; off > 0; off >>= 1)
                p += __shfl_xor_sync(0xFFFFFFFFu, p, off);
            if (l == leader) {
                unsigned long long b = 1ull << id;
                if (p > 0.f) sign |= b; else sign &= ~b;
                flag &= flag - 1;
            }
        }

        // ---- q-projection (reuse acc) ----
        #pragma unroll
        for (int mt = 0; mt < 3; mt++)
            #pragma unroll
            for (int nt = 0; nt < 4; nt++)
                #pragma unroll
                for (int j = 0; j < 4; j++) acc[mt][nt][j] = 0.f;
        #pragma unroll
        for (int ks = 0; ks < 8; ks++) {
            uint32_t A[3][4];
            uint32_t qa = a_base + (Q_OFF - K_OFF) + ks * 32;
            ldsm_x4(A[0], qa);
            ldsm_x4(A[1], qa + 16 * 272);
            ldsm_x4(A[2], qa + 32 * 272);
            #pragma unroll
            for (int g = 0; g < 2; g++) {
                uint32_t B[4];
                ldsm_x4(B, b_base + g * (16 * 272) + ks * 32);
                #pragma unroll
                for (int mt = 0; mt < 3; mt++) {
                    mma16816(acc[mt][2 * g],     A[mt], B[0], B[1]);
                    mma16816(acc[mt][2 * g + 1], A[mt], B[2], B[3]);
                }
            }
        }

        // ---- epilogue: signed reduction over p, deterministic ----
        float* est = (float*)smem;   // [96][8]
        #pragma unroll
        for (int mt = 0; mt < 3; mt++)
            #pragma unroll
            for (int h = 0; h < 2; h++) {
                float s = 0.f;
                #pragma unroll
                for (int nt = 0; nt < 4; nt++)
                    #pragma unroll
                    for (int jj = 0; jj < 2; jj++) {
                        int j = h * 2 + jj;
                        int id = mt * 16 + nt * 4 + j;
                        float v = acc[mt][nt][j];
                        s += ((sign >> id) & 1ull) ? v : -v;
                    }
                s += __shfl_xor_sync(0xFFFFFFFFu, s, 1);
                s += __shfl_xor_sync(0xFFFFFFFFu, s, 2);
                if ((l & 3) == 0) {
                    int row = wm * 48 + mt * 16 + h * 8 + (l >> 2);
                    est[row * 8 + wn] = s;
                }
            }
        __syncthreads();
        if (tid < ROWS) {
            int tok = tok_base + tid;
            if (tok < ntok) {
                const float* e = est + tid * 8;
                out[tok] = SCALE * (((e[0] + e[1]) + (e[2] + e[3]))
                                  + ((e[4] + e[5]) + (e[6] + e[7])));
            }
        }

        // ---- next tile's staging must be complete & visible ----
        asm volatile("cp.async.wait_group 0;" ::: "memory");
        __syncthreads();
    }
}

extern "C" void kernel_launch(void* const* d_in, const int* in_sizes, int n_in,
                              void* d_out, int out_size) {
    const float* q = (const float*)d_in[0];
    const float* k = (const float*)d_in[1];
    const float* S = (const float*)d_in[2];
    float* out = (float*)d_out;

    int ntok = in_sizes[0] / 128;
    int ntiles = (ntok + ROWS - 1) / ROWS;
    int grid = ntiles < 148 ? ntiles : 148;

    qjl_conv_S<<<16, 256>>>(S);

    cudaFuncSetAttribute(qjl_fused, cudaFuncAttributeMaxDynamicSharedMemorySize,
                         SMEM_TOTAL);
    qjl_fused<<<grid, THREADS, SMEM_TOTAL>>>(q, k, S, out, ntok, ntiles);
}